// round 3
// baseline (speedup 1.0000x reference)
#include <cuda_runtime.h>

// B=2048, D=3706, total=7,589,888 (divisible by 1024 -> no tail for this shape)
// inputs: d_in[0] fake [B,D] f32; d_in[1] minb [D] f32; d_in[2] lens [D,4] f32
// output: dist f32 [B,D,6] then val f32 [B,D]
//
// b0=min[d]; b_{k+1}=b_k+relu(len[d,k])+1e-4; dist = strict one-hot; val = dist . [0..5]
//
// R3: 4 elems/thread (stride-256 interleave keeps smem 2-way conflicts),
//     streaming ld/st hints (__ldcs/__stcs), smem-coalesced float4 flush.

#define EPSK 1e-4f
#define TPB  256
#define EPT  4                      // elements per thread
#define EPB  (TPB * EPT)            // 1024 elements per block

__global__ void __launch_bounds__(TPB)
discret_kernel(const float* __restrict__ fake,
               const float* __restrict__ minb,
               const float4* __restrict__ lens,
               float* __restrict__ out_dist,   // [B*D*6]
               float* __restrict__ out_val,    // [B*D]
               int total, int D)
{
    __shared__ float sdist[EPB * 6];    // 24 KB

    const int t     = threadIdx.x;
    const int base  = blockIdx.x * EPB;       // first element of this block

    // column index of element (base + t); subsequent elements add 256 each
    int m = (base + t) % D;

    #pragma unroll
    for (int i = 0; i < EPT; i++) {
        int e   = t + i * TPB;                 // element within block (interleaved)
        int idx = base + e;
        int d   = m + i * TPB;                 // 256*i < D so at most one wrap per step sum
        // reduce mod D (i*256 <= 768 < D, but accumulated wrap handled below)
        while (d >= D) d -= D;

        float d0 = 0.f, d1 = 0.f, d2 = 0.f, d3 = 0.f, d4 = 0.f, d5 = 0.f;

        if (idx < total) {
            float a  = __ldcs(&fake[idx]);
            float4 L = __ldg(&lens[d]);
            float b0 = __ldg(&minb[d]);
            float b1 = b0 + fmaxf(L.x, 0.0f) + EPSK;
            float b2 = b1 + fmaxf(L.y, 0.0f) + EPSK;
            float b3 = b2 + fmaxf(L.z, 0.0f) + EPSK;
            float b4 = b3 + fmaxf(L.w, 0.0f) + EPSK;

            d0 = (a < b0)           ? 1.0f : 0.0f;
            d1 = (a > b0 && a < b1) ? 1.0f : 0.0f;
            d2 = (a > b1 && a < b2) ? 1.0f : 0.0f;
            d3 = (a > b2 && a < b3) ? 1.0f : 0.0f;
            d4 = (a > b3 && a < b4) ? 1.0f : 0.0f;
            d5 = (a > b4)           ? 1.0f : 0.0f;

            float v = d1 + 2.0f * d2 + 3.0f * d3 + 4.0f * d4 + 5.0f * d5;
            __stcs(&out_val[idx], v);
        }

        // stage: word addr = 6*e + j ; lane stride 6 words -> 2-way bank conflict
        float* s = sdist + e * 6;
        s[0] = d0; s[1] = d1; s[2] = d2; s[3] = d3; s[4] = d4; s[5] = d5;
    }

    __syncthreads();

    int n_valid = total - base;
    if (n_valid >= EPB) {
        // flush 6144 floats = 1536 float4, fully coalesced, streaming
        const float4* s4 = reinterpret_cast<const float4*>(sdist);
        float4* g4 = reinterpret_cast<float4*>(out_dist + (size_t)base * 6);
        #pragma unroll
        for (int k = 0; k < (EPB * 6) / 4 / TPB; k++)
            __stcs(&g4[k * TPB + t], s4[k * TPB + t]);
    } else {
        float* g = out_dist + (size_t)base * 6;
        for (int i = t; i < n_valid * 6; i += TPB)
            __stcs(&g[i], sdist[i]);
    }
}

extern "C" void kernel_launch(void* const* d_in, const int* in_sizes, int n_in,
                              void* d_out, int out_size)
{
    const float*  fake = (const float*)d_in[0];
    const float*  minb = (const float*)d_in[1];
    const float4* lens = (const float4*)d_in[2];

    int total = in_sizes[0];          // B*D
    int D     = in_sizes[1];          // 3706

    float* out  = (float*)d_out;
    float* dist = out;                          // [B*D*6]
    float* val  = out + (size_t)total * 6;      // [B*D]

    int blocks = (total + EPB - 1) / EPB;
    discret_kernel<<<blocks, TPB>>>(fake, minb, lens, dist, val, total, D);
}

// round 4
// speedup vs baseline: 1.3379x; 1.3379x over previous
#include <cuda_runtime.h>

// B=2048, D=3706, total=B*D=7,589,888 (divisible by 256)
// inputs: d_in[0] fake [B,D] f32; d_in[1] minb [D] f32; d_in[2] lens [D,4] f32
// output: dist f32 [B,D,6] then val f32 [B,D]
//
// b0=min[d]; b_{k+1}=b_k+relu(len[d,k])+1e-4 (strictly increasing)
// dist[r] = (r==0 || a>b[r-1]) && (r==5 || a<b[r]); a==b_k -> all zeros
// val = sum r*dist[r]
//
// R4 = R2 (best structure) + evict-first (__stcs) on ALL output stores.
// Rationale: 212MB write stream evict-normal was flushing the 30MB fake
// working set out of L2 between graph replays; streaming stores keep fake
// L2-resident and let dirty lines drain immediately.

#define EPSK 1e-4f
#define TPB 256

__global__ void __launch_bounds__(TPB)
discret_kernel(const float* __restrict__ fake,
               const float* __restrict__ minb,
               const float4* __restrict__ lens,
               float* __restrict__ out_dist,   // [B*D*6]
               float* __restrict__ out_val,    // [B*D]
               int total, int D)
{
    __shared__ float sdist[TPB * 6];   // 6 KB

    int t   = threadIdx.x;
    int idx = blockIdx.x * TPB + t;

    float d0 = 0.f, d1 = 0.f, d2 = 0.f, d3 = 0.f, d4 = 0.f, d5 = 0.f;

    if (idx < total) {
        int d = idx % D;

        float a  = fake[idx];              // default policy: stays in L2 across replays
        float4 L = __ldg(&lens[d]);
        float b0 = __ldg(&minb[d]);
        float b1 = b0 + fmaxf(L.x, 0.0f) + EPSK;
        float b2 = b1 + fmaxf(L.y, 0.0f) + EPSK;
        float b3 = b2 + fmaxf(L.z, 0.0f) + EPSK;
        float b4 = b3 + fmaxf(L.w, 0.0f) + EPSK;

        d0 = (a < b0)           ? 1.0f : 0.0f;
        d1 = (a > b0 && a < b1) ? 1.0f : 0.0f;
        d2 = (a > b1 && a < b2) ? 1.0f : 0.0f;
        d3 = (a > b2 && a < b3) ? 1.0f : 0.0f;
        d4 = (a > b3 && a < b4) ? 1.0f : 0.0f;
        d5 = (a > b4)           ? 1.0f : 0.0f;

        float v = d1 + 2.0f * d2 + 3.0f * d3 + 4.0f * d4 + 5.0f * d5;
        __stcs(&out_val[idx], v);          // evict-first
    }

    // stage into smem (stride-6 word writes: benign 2-way bank conflict)
    float* s = sdist + t * 6;
    s[0] = d0; s[1] = d1; s[2] = d2; s[3] = d3; s[4] = d4; s[5] = d5;
    __syncthreads();

    int block_first = blockIdx.x * TPB;
    int n_valid = total - block_first;
    if (n_valid >= TPB) {
        // full block: flush 1536 floats = 384 float4, fully coalesced, evict-first
        const float4* s4 = reinterpret_cast<const float4*>(sdist);
        float4* g4 = reinterpret_cast<float4*>(out_dist + (size_t)block_first * 6);
        #pragma unroll
        for (int i = t; i < (TPB * 6) / 4; i += TPB)
            __stcs(&g4[i], s4[i]);
    } else {
        // tail block (unused for this shape, kept for generality)
        float* g = out_dist + (size_t)block_first * 6;
        for (int i = t; i < n_valid * 6; i += TPB)
            __stcs(&g[i], sdist[i]);
    }
}

extern "C" void kernel_launch(void* const* d_in, const int* in_sizes, int n_in,
                              void* d_out, int out_size)
{
    const float*  fake = (const float*)d_in[0];
    const float*  minb = (const float*)d_in[1];
    const float4* lens = (const float4*)d_in[2];

    int total = in_sizes[0];          // B*D
    int D     = in_sizes[1];          // 3706

    float* out  = (float*)d_out;
    float* dist = out;                          // [B*D*6]
    float* val  = out + (size_t)total * 6;      // [B*D]

    int blocks = (total + TPB - 1) / TPB;
    discret_kernel<<<blocks, TPB>>>(fake, minb, lens, dist, val, total, D);
}